// round 1
// baseline (speedup 1.0000x reference)
#include <cuda_runtime.h>
#include <math.h>

// ---------------------------------------------------------------------------
// Encoder_28802050687022: 3-stage (strided conv k4s2p1 + ConvGRU k5s1p2) scan
// Input: [B=8, T=12, C=1, 128,128] fp32.
// Stage1: 1->64ch @64x64, Stage2: 64->128ch @32x32, Stage3: 128->128ch @16x16
// Outputs concatenated: state1 [8,64,64,64], state2 [8,128,32,32], state3 [8,128,16,16]
// ---------------------------------------------------------------------------

#define TSTEPS 12
#define BATCH  8

// Scratch (static device globals — no allocation allowed)
__device__ float g_seq1[(size_t)TSTEPS * BATCH * 64 * 64 * 64];   // 25.2M floats
__device__ float g_seq2[(size_t)TSTEPS * BATCH * 128 * 32 * 32];  // 12.6M floats
__device__ float g_xt  [(size_t)BATCH * 64 * 64 * 64];            // max xt (stage1)
__device__ float g_zr  [(size_t)BATCH * 128 * 64 * 64];           // max zr (stage1)
__device__ float g_h3a [(size_t)BATCH * 128 * 16 * 16];
__device__ float g_h3b [(size_t)BATCH * 128 * 16 * 16];
__device__ float g_zero[(size_t)BATCH * 64 * 64 * 64];            // zero h0 (max h size)

__global__ void zerok(float* p, int n) {
    int i = blockIdx.x * blockDim.x + threadIdx.x;
    if (i < n) p[i] = 0.0f;
}

__global__ void copyk(float* __restrict__ dst, const float* __restrict__ src, int n) {
    int i = blockIdx.x * blockDim.x + threadIdx.x;
    if (i < n) dst[i] = src[i];
}

// ---------------------------------------------------------------------------
// Strided conv: k=4, stride=2, pad=1.  out[b,o,y,x] = bias[o] + sum_{i,kh,kw}
//   in[b,i,2y-1+kh,2x-1+kw] * w[o,i,kh,kw]
// Each thread: one output pixel, OC output channels.
// ---------------------------------------------------------------------------
template <int TX, int TY, int OC>
__global__ void conv4s2(const float* __restrict__ in, long long inBatchStride,
                        const float* __restrict__ w, const float* __restrict__ bias,
                        float* __restrict__ out,
                        int Cin, int Cout, int Hin, int Win)
{
    const int Hout = Hin >> 1, Wout = Win >> 1;
    const int ocGroups = Cout / OC;
    const int b   = blockIdx.z / ocGroups;
    const int ocb = blockIdx.z % ocGroups;
    const int y0  = blockIdx.y * TY;
    const int x0  = blockIdx.x * TX;

    constexpr int IW = 2 * TX + 2;
    constexpr int IH = 2 * TY + 2;
    __shared__ float s_in[IH * IW];
    __shared__ float s_w[OC * 16];

    const int tid = threadIdx.y * TX + threadIdx.x;
    const int nth = TX * TY;

    float acc[OC];
#pragma unroll
    for (int oc = 0; oc < OC; oc++) acc[oc] = 0.0f;

    for (int ic = 0; ic < Cin; ic++) {
        const float* src = in + (long long)b * inBatchStride + (long long)ic * Hin * Win;
        for (int idx = tid; idx < IH * IW; idx += nth) {
            int iy = 2 * y0 - 1 + idx / IW;
            int ix = 2 * x0 - 1 + idx % IW;
            s_in[idx] = (iy >= 0 && iy < Hin && ix >= 0 && ix < Win) ? src[(long long)iy * Win + ix] : 0.0f;
        }
        for (int idx = tid; idx < OC * 16; idx += nth) {
            int oc = idx / 16, k = idx % 16;
            s_w[idx] = w[(((long long)(ocb * OC + oc)) * Cin + ic) * 16 + k];
        }
        __syncthreads();

#pragma unroll
        for (int kh = 0; kh < 4; kh++) {
#pragma unroll
            for (int kw = 0; kw < 4; kw++) {
                float inv = s_in[(2 * threadIdx.y + kh) * IW + 2 * threadIdx.x + kw];
#pragma unroll
                for (int oc = 0; oc < OC; oc++)
                    acc[oc] = fmaf(inv, s_w[oc * 16 + kh * 4 + kw], acc[oc]);
            }
        }
        __syncthreads();
    }

    const int y = y0 + threadIdx.y, x = x0 + threadIdx.x;
#pragma unroll
    for (int oc = 0; oc < OC; oc++) {
        int c = ocb * OC + oc;
        out[(((long long)b * Cout + c) * Hout + y) * Wout + x] = acc[oc] + bias[c];
    }
}

// ---------------------------------------------------------------------------
// 5x5 conv, stride 1, pad 2, over logical concat of two sources:
//   channels [0,Cx) from xin, [Cx, Cx+Ch) from hin.
// APPLY_R: multiply h-part inputs by r = zr channel ic (ic in [Cx, Cx+Ch)).
// EPI 0 (sigmoid): out = sigmoid(acc + b)            -> zr buffer
// EPI 1 (GRU):     out = (1-z)*h_prev + z*tanh(acc+b), z = zr[ch c]
// Thread computes 4 consecutive y rows x OC output channels.
// ---------------------------------------------------------------------------
template <int TX, int TY, int OC, int EPI, bool APPLY_R>
__global__ void conv5k(const float* __restrict__ xin, const float* __restrict__ hin,
                       int Cx, int Ch,
                       const float* __restrict__ w, const float* __restrict__ bias,
                       const float* __restrict__ zr, const float* __restrict__ hprev,
                       float* __restrict__ out,
                       int Cout, int H, int W)
{
    constexpr int RY = TY / 4;
    constexpr int IW = TX + 4;
    constexpr int IH = TY + 4;
    const int ocGroups = Cout / OC;
    const int b   = blockIdx.z / ocGroups;
    const int ocb = blockIdx.z % ocGroups;
    const int y0  = blockIdx.y * TY;
    const int x0  = blockIdx.x * TX;

    __shared__ float s_in[IH * IW];
    __shared__ float s_w[OC * 25];

    const int tid = threadIdx.y * TX + threadIdx.x;
    const int nth = TX * RY;
    const int Cin = Cx + Ch;
    const long long HW = (long long)H * W;

    float acc[4][OC];
#pragma unroll
    for (int i = 0; i < 4; i++)
#pragma unroll
        for (int oc = 0; oc < OC; oc++) acc[i][oc] = 0.0f;

    for (int ic = 0; ic < Cin; ic++) {
        const float* src = (ic < Cx) ? (xin + ((long long)b * Cx + ic) * HW)
                                     : (hin + ((long long)b * Ch + (ic - Cx)) * HW);
        const float* rsrc = nullptr;
        if (APPLY_R && ic >= Cx) rsrc = zr + ((long long)b * Cin + ic) * HW;  // zr has Cin=2C channels

        for (int idx = tid; idx < IH * IW; idx += nth) {
            int iy = y0 - 2 + idx / IW;
            int ix = x0 - 2 + idx % IW;
            float v = 0.0f;
            if (iy >= 0 && iy < H && ix >= 0 && ix < W) {
                long long p = (long long)iy * W + ix;
                v = src[p];
                if (APPLY_R && ic >= Cx) v *= rsrc[p];
            }
            s_in[idx] = v;
        }
        for (int idx = tid; idx < OC * 25; idx += nth) {
            int oc = idx / 25, k = idx % 25;
            s_w[idx] = w[(((long long)(ocb * OC + oc)) * Cin + ic) * 25 + k];
        }
        __syncthreads();

#pragma unroll
        for (int kh = 0; kh < 5; kh++) {
#pragma unroll
            for (int kw = 0; kw < 5; kw++) {
                float inv[4];
#pragma unroll
                for (int i = 0; i < 4; i++)
                    inv[i] = s_in[(threadIdx.y * 4 + i + kh) * IW + threadIdx.x + kw];
#pragma unroll
                for (int oc = 0; oc < OC; oc++) {
                    float wv = s_w[oc * 25 + kh * 5 + kw];
#pragma unroll
                    for (int i = 0; i < 4; i++)
                        acc[i][oc] = fmaf(inv[i], wv, acc[i][oc]);
                }
            }
        }
        __syncthreads();
    }

#pragma unroll
    for (int oc = 0; oc < OC; oc++) {
        const int c = ocb * OC + oc;
        const float bv = bias[c];
#pragma unroll
        for (int i = 0; i < 4; i++) {
            const int y = y0 + threadIdx.y * 4 + i;
            const int x = x0 + threadIdx.x;
            const long long pix  = (long long)y * W + x;
            const long long oidx = ((long long)b * Cout + c) * HW + pix;
            float a = acc[i][oc] + bv;
            if (EPI == 0) {
                out[oidx] = 1.0f / (1.0f + expf(-a));
            } else {
                float z  = zr[((long long)b * (2 * Cout) + c) * HW + pix];
                float hp = hprev[oidx];
                out[oidx] = (1.0f - z) * hp + z * tanhf(a);
            }
        }
    }
}

// ---------------------------------------------------------------------------

extern "C" void kernel_launch(void* const* d_in, const int* in_sizes, int n_in,
                              void* d_out, int out_size)
{
    const float* input   = (const float*)d_in[0];
    const float* c1_w    = (const float*)d_in[1];
    const float* c1_b    = (const float*)d_in[2];
    const float* g1_zr_w = (const float*)d_in[3];
    const float* g1_zr_b = (const float*)d_in[4];
    const float* g1_h_w  = (const float*)d_in[5];
    const float* g1_h_b  = (const float*)d_in[6];
    const float* c2_w    = (const float*)d_in[7];
    const float* c2_b    = (const float*)d_in[8];
    const float* g2_zr_w = (const float*)d_in[9];
    const float* g2_zr_b = (const float*)d_in[10];
    const float* g2_h_w  = (const float*)d_in[11];
    const float* g2_h_b  = (const float*)d_in[12];
    const float* c3_w    = (const float*)d_in[13];
    const float* c3_b    = (const float*)d_in[14];
    const float* g3_zr_w = (const float*)d_in[15];
    const float* g3_zr_b = (const float*)d_in[16];
    const float* g3_h_w  = (const float*)d_in[17];
    const float* g3_h_b  = (const float*)d_in[18];

    float *seq1, *seq2, *xt, *zr, *h3a, *h3b, *zero0;
    cudaGetSymbolAddress((void**)&seq1,  g_seq1);
    cudaGetSymbolAddress((void**)&seq2,  g_seq2);
    cudaGetSymbolAddress((void**)&xt,    g_xt);
    cudaGetSymbolAddress((void**)&zr,    g_zr);
    cudaGetSymbolAddress((void**)&h3a,   g_h3a);
    cudaGetSymbolAddress((void**)&h3b,   g_h3b);
    cudaGetSymbolAddress((void**)&zero0, g_zero);

    // zero h0 buffer (deterministic every call)
    {
        int nz = BATCH * 64 * 64 * 64;
        zerok<<<(nz + 255) / 256, 256>>>(zero0, nz);
    }

    const size_t S1 = (size_t)BATCH * 64 * 64 * 64;    // per-t stage1 seq slice
    const size_t S2 = (size_t)BATCH * 128 * 32 * 32;   // per-t stage2 seq slice

    // ---------------- Stage 1: 1 -> 64ch, 128x128 -> 64x64 ----------------
    {
        const float* hprev = zero0;
        for (int t = 0; t < TSTEPS; t++) {
            // conv k4s2p1: input [B,(T),1,128,128] slice
            conv4s2<16, 8, 8><<<dim3(4, 8, BATCH * (64 / 8)), dim3(16, 8)>>>(
                input + (size_t)t * 128 * 128, (long long)TSTEPS * 128 * 128,
                c1_w, c1_b, xt, 1, 64, 128, 128);
            // zr = sigmoid(conv5([xt,h]))
            conv5k<32, 16, 8, 0, false><<<dim3(64 / 32, 64 / 16, BATCH * (128 / 8)), dim3(32, 4)>>>(
                xt, hprev, 64, 64, g1_zr_w, g1_zr_b, nullptr, nullptr, zr, 128, 64, 64);
            // h_new = (1-z)h + z tanh(conv5([xt, r*h]))
            float* hout = seq1 + (size_t)t * S1;
            conv5k<32, 16, 8, 1, true><<<dim3(64 / 32, 64 / 16, BATCH * (64 / 8)), dim3(32, 4)>>>(
                xt, hprev, 64, 64, g1_h_w, g1_h_b, zr, hprev, hout, 64, 64, 64);
            hprev = hout;
        }
    }

    // ---------------- Stage 2: 64 -> 128ch, 64x64 -> 32x32 ----------------
    {
        const float* hprev = zero0;
        for (int t = 0; t < TSTEPS; t++) {
            conv4s2<16, 8, 8><<<dim3(2, 4, BATCH * (128 / 8)), dim3(16, 8)>>>(
                seq1 + (size_t)t * S1, (long long)64 * 64 * 64,
                c2_w, c2_b, xt, 64, 128, 64, 64);
            conv5k<32, 16, 8, 0, false><<<dim3(1, 2, BATCH * (256 / 8)), dim3(32, 4)>>>(
                xt, hprev, 128, 128, g2_zr_w, g2_zr_b, nullptr, nullptr, zr, 256, 32, 32);
            float* hout = seq2 + (size_t)t * S2;
            conv5k<32, 16, 8, 1, true><<<dim3(1, 2, BATCH * (128 / 8)), dim3(32, 4)>>>(
                xt, hprev, 128, 128, g2_h_w, g2_h_b, zr, hprev, hout, 128, 32, 32);
            hprev = hout;
        }
    }

    // ---------------- Stage 3: 128 -> 128ch, 32x32 -> 16x16 ----------------
    float* h3final = nullptr;
    {
        const float* hprev = zero0;
        float* bufs[2] = { h3a, h3b };
        for (int t = 0; t < TSTEPS; t++) {
            conv4s2<16, 8, 8><<<dim3(1, 2, BATCH * (128 / 8)), dim3(16, 8)>>>(
                seq2 + (size_t)t * S2, (long long)128 * 32 * 32,
                c3_w, c3_b, xt, 128, 128, 32, 32);
            conv5k<16, 16, 8, 0, false><<<dim3(1, 1, BATCH * (256 / 8)), dim3(16, 4)>>>(
                xt, hprev, 128, 128, g3_zr_w, g3_zr_b, nullptr, nullptr, zr, 256, 16, 16);
            float* hout = bufs[t & 1];
            conv5k<16, 16, 8, 1, true><<<dim3(1, 1, BATCH * (128 / 8)), dim3(16, 4)>>>(
                xt, hprev, 128, 128, g3_h_w, g3_h_b, zr, hprev, hout, 128, 16, 16);
            hprev = hout;
            h3final = hout;
        }
    }

    // ---------------- Gather outputs: state1 | state2 | state3 -------------
    float* out = (float*)d_out;
    {
        int n1 = (int)S1;                       // 2,097,152
        int n2 = (int)S2;                       // 1,048,576
        int n3 = BATCH * 128 * 16 * 16;         //   262,144
        copyk<<<(n1 + 255) / 256, 256>>>(out, seq1 + (size_t)(TSTEPS - 1) * S1, n1);
        copyk<<<(n2 + 255) / 256, 256>>>(out + n1, seq2 + (size_t)(TSTEPS - 1) * S2, n2);
        copyk<<<(n3 + 255) / 256, 256>>>(out + n1 + n2, h3final, n3);
    }
}

// round 2
// speedup vs baseline: 1.7937x; 1.7937x over previous
#include <cuda_runtime.h>
#include <math.h>
#include <stdint.h>

#define TSTEPS 12
#define BATCH  8

// ---------------- scratch (static device globals; no allocation allowed) ----
__device__ float g_seq1[(size_t)TSTEPS * BATCH * 64 * 64 * 64];   // 25.2M
__device__ float g_seq2[(size_t)TSTEPS * BATCH * 128 * 32 * 32];  // 12.6M
__device__ float g_xts1[(size_t)TSTEPS * BATCH * 64 * 64 * 64];   // 25.2M
__device__ float g_xts2[(size_t)TSTEPS * BATCH * 128 * 32 * 32];  // 12.6M
__device__ float g_xts3[(size_t)TSTEPS * BATCH * 128 * 16 * 16];  // 3.1M
__device__ float g_zr  [(size_t)BATCH * 128 * 64 * 64];           // 4.19M (max zr)
__device__ float g_rh  [(size_t)BATCH * 64 * 64 * 64];            // 2.1M  (max rh)
__device__ float g_part[(size_t)4194304];                          // split-K partials
__device__ float g_h3a [(size_t)BATCH * 128 * 16 * 16];
__device__ float g_h3b [(size_t)BATCH * 128 * 16 * 16];
__device__ float g_zero[(size_t)BATCH * 64 * 64 * 64];            // zero h0 (max)

__global__ void zerok(float* p, int n) {
    int i = blockIdx.x * blockDim.x + threadIdx.x;
    if (i < n) p[i] = 0.0f;
}
__global__ void copyk(float* __restrict__ dst, const float* __restrict__ src, int n) {
    int i = blockIdx.x * blockDim.x + threadIdx.x;
    if (i < n) dst[i] = src[i];
}

// ---------------- cp.async helpers ------------------------------------------
__device__ __forceinline__ void cp4(uint32_t saddr, const float* g, bool ok) {
    int sz = ok ? 4 : 0;
    asm volatile("cp.async.ca.shared.global [%0], [%1], 4, %2;\n"
                 :: "r"(saddr), "l"(g), "r"(sz));
}
__device__ __forceinline__ void cpCommit() {
    asm volatile("cp.async.commit_group;\n" ::: "memory");
}
template <int N>
__device__ __forceinline__ void cpWait() {
    asm volatile("cp.async.wait_group %0;\n" :: "n"(N) : "memory");
}

// ---------------------------------------------------------------------------
// Strided conv k4 s2 p1, batched over T.
// Each thread: one output pixel x OC channels.
// blockIdx.z = ((t*BATCH + b)*ocG + ocb)
// ---------------------------------------------------------------------------
template <int TX, int TY, int OC>
__global__ void conv4s2(const float* __restrict__ in,
                        long long strideB, long long strideT,
                        const float* __restrict__ w, const float* __restrict__ bias,
                        float* __restrict__ out,
                        int Cin, int Cout, int Hin, int Win)
{
    const int Hout = Hin >> 1, Wout = Win >> 1;
    const int ocG = Cout / OC;
    int z = blockIdx.z;
    const int ocb = z % ocG; z /= ocG;
    const int b   = z % BATCH;
    const int t   = z / BATCH;
    const int y0  = blockIdx.y * TY;
    const int x0  = blockIdx.x * TX;

    constexpr int IW = 2 * TX + 2;
    constexpr int IH = 2 * TY + 2;
    __shared__ float s_in[IH * IW];
    __shared__ float s_w[OC * 16];

    const int tid = threadIdx.y * TX + threadIdx.x;
    const int nth = TX * TY;

    const float* base = in + (long long)b * strideB + (long long)t * strideT;

    float acc[OC];
#pragma unroll
    for (int oc = 0; oc < OC; oc++) acc[oc] = 0.0f;

    for (int ic = 0; ic < Cin; ic++) {
        const float* src = base + (long long)ic * Hin * Win;
        for (int idx = tid; idx < IH * IW; idx += nth) {
            int iy = 2 * y0 - 1 + idx / IW;
            int ix = 2 * x0 - 1 + idx % IW;
            s_in[idx] = (iy >= 0 && iy < Hin && ix >= 0 && ix < Win)
                            ? src[(long long)iy * Win + ix] : 0.0f;
        }
        for (int idx = tid; idx < OC * 16; idx += nth) {
            int oc = idx / 16, k = idx % 16;
            s_w[idx] = w[(((long long)(ocb * OC + oc)) * Cin + ic) * 16 + k];
        }
        __syncthreads();
#pragma unroll
        for (int kh = 0; kh < 4; kh++)
#pragma unroll
            for (int kw = 0; kw < 4; kw++) {
                float inv = s_in[(2 * threadIdx.y + kh) * IW + 2 * threadIdx.x + kw];
#pragma unroll
                for (int oc = 0; oc < OC; oc++)
                    acc[oc] = fmaf(inv, s_w[oc * 16 + kh * 4 + kw], acc[oc]);
            }
        __syncthreads();
    }

    const int y = y0 + threadIdx.y, x = x0 + threadIdx.x;
#pragma unroll
    for (int oc = 0; oc < OC; oc++) {
        int c = ocb * OC + oc;
        out[(((long long)(t * BATCH + b) * Cout + c) * Hout + y) * Wout + x] = acc[oc] + bias[c];
    }
}

// ---------------------------------------------------------------------------
// 5x5 conv s1 p2, double-buffered cp.async, two input sources (logical concat),
// optional split-K over input channels.
// EPI 0: fused sigmoid -> zr buffer, and for r-half write rh = r*hprev. (KS==1)
// EPI 2: raw partial write (no bias) to out[ks][b][c][hw].
// Thread computes 4 y-rows x OC channels. Block (TX, TY/4).
// blockIdx.z = ((b*ocG + ocb)*KS + ks)
// ---------------------------------------------------------------------------
template <int TX, int TY, int OC, int EPI>
__global__ void conv5(const float* __restrict__ src0, int C0,
                      const float* __restrict__ src1, int C1,
                      const float* __restrict__ w, const float* __restrict__ bias,
                      float* __restrict__ out, float* __restrict__ rhOut,
                      int Cout, int H, int W, int ocG, int KS, int chunk)
{
    constexpr int IW = TX + 4, IH = TY + 4, IN = IH * IW, WN = OC * 25;
    __shared__ float s_in[2 * IN];
    __shared__ float s_w[2 * WN];

    int z = blockIdx.z;
    const int ks  = z % KS;  z /= KS;
    const int ocb = z % ocG;
    const int b   = z / ocG;
    const int y0  = blockIdx.y * TY;
    const int x0  = blockIdx.x * TX;
    const int tid = threadIdx.y * TX + threadIdx.x;
    const int nth = TX * (TY / 4);
    const int Cin = C0 + C1;
    const long long HW = (long long)H * W;
    const int icBeg = ks * chunk, icEnd = icBeg + chunk;

    const uint32_t sib = (uint32_t)__cvta_generic_to_shared(s_in);
    const uint32_t swb = (uint32_t)__cvta_generic_to_shared(s_w);

    auto fill = [&](int buf, int ic) {
        const float* src = (ic < C0) ? src0 + ((long long)b * C0 + ic) * HW
                                     : src1 + ((long long)b * C1 + (ic - C0)) * HW;
        for (int idx = tid; idx < IN; idx += nth) {
            int rr = idx / IW, cc = idx - rr * IW;
            int iy = y0 - 2 + rr, ix = x0 - 2 + cc;
            bool ok = (iy >= 0) && (iy < H) && (ix >= 0) && (ix < W);
            const float* g = ok ? (src + (long long)iy * W + ix) : src;
            cp4(sib + (uint32_t)(buf * IN + idx) * 4u, g, ok);
        }
        for (int idx = tid; idx < WN; idx += nth) {
            int oc = idx / 25, k = idx - oc * 25;
            const float* g = w + (((long long)(ocb * OC + oc)) * Cin + ic) * 25 + k;
            cp4(swb + (uint32_t)(buf * WN + idx) * 4u, g, true);
        }
    };

    float acc[4][OC];
#pragma unroll
    for (int i = 0; i < 4; i++)
#pragma unroll
        for (int oc = 0; oc < OC; oc++) acc[i][oc] = 0.0f;

    fill(0, icBeg);
    cpCommit();

    for (int ic = icBeg; ic < icEnd; ic++) {
        const int cur = (ic - icBeg) & 1;
        if (ic + 1 < icEnd) fill(cur ^ 1, ic + 1);
        cpCommit();
        cpWait<1>();
        __syncthreads();

        const float* si = s_in + cur * IN;
        const float* sw = s_w + cur * WN;
#pragma unroll
        for (int kh = 0; kh < 5; kh++)
#pragma unroll
            for (int kw = 0; kw < 5; kw++) {
                float inv[4];
#pragma unroll
                for (int i = 0; i < 4; i++)
                    inv[i] = si[(threadIdx.y * 4 + i + kh) * IW + threadIdx.x + kw];
#pragma unroll
                for (int oc = 0; oc < OC; oc++) {
                    float wv = sw[oc * 25 + kh * 5 + kw];
#pragma unroll
                    for (int i = 0; i < 4; i++)
                        acc[i][oc] = fmaf(inv[i], wv, acc[i][oc]);
                }
            }
        __syncthreads();
    }

#pragma unroll
    for (int oc = 0; oc < OC; oc++) {
        const int c = ocb * OC + oc;
#pragma unroll
        for (int i = 0; i < 4; i++) {
            const int y = y0 + threadIdx.y * 4 + i;
            const int x = x0 + threadIdx.x;
            const long long pix = (long long)y * W + x;
            if (EPI == 0) {
                // fused zr: sigmoid + rh for the r half. KS==1.
                float a = acc[i][oc] + bias[c];
                float s = 1.0f / (1.0f + expf(-a));
                out[((long long)b * Cout + c) * HW + pix] = s;
                const int Chalf = Cout >> 1;
                if (c >= Chalf) {
                    long long hidx = ((long long)b * Chalf + (c - Chalf)) * HW + pix;
                    rhOut[hidx] = s * src1[hidx];  // src1 == hprev
                }
            } else {
                // raw partial (bias added in epilogue)
                out[((long long)(ks * BATCH + b) * Cout + c) * HW + pix] = acc[i][oc];
            }
        }
    }
}

// ---------------------------------------------------------------------------
// Split-K epilogues (memory-bound elementwise)
// ---------------------------------------------------------------------------
__global__ void zrEpiK(const float* __restrict__ part, int KS,
                       const float* __restrict__ bias, const float* __restrict__ hprev,
                       float* __restrict__ zrOut, float* __restrict__ rhOut,
                       int C2, long long HW)
{
    const long long n = (long long)BATCH * C2 * HW;
    long long i = (long long)blockIdx.x * blockDim.x + threadIdx.x;
    if (i >= n) return;
    float s = 0.0f;
    for (int k = 0; k < KS; k++) s += part[(long long)k * n + i];
    const int c = (int)((i / HW) % C2);
    s += bias[c];
    float sg = 1.0f / (1.0f + expf(-s));
    zrOut[i] = sg;
    const int C = C2 >> 1;
    if (c >= C) {
        long long b = i / (HW * C2);
        long long pix = i % HW;
        long long hidx = (b * C + (c - C)) * HW + pix;
        rhOut[hidx] = sg * hprev[hidx];
    }
}

__global__ void hEpiK(const float* __restrict__ part, int KS,
                      const float* __restrict__ bias, const float* __restrict__ zr,
                      const float* __restrict__ hprev, float* __restrict__ out,
                      int C, long long HW)
{
    const long long n = (long long)BATCH * C * HW;
    long long i = (long long)blockIdx.x * blockDim.x + threadIdx.x;
    if (i >= n) return;
    float s = 0.0f;
    for (int k = 0; k < KS; k++) s += part[(long long)k * n + i];
    const int c = (int)((i / HW) % C);
    long long b = i / (HW * C);
    long long pix = i % HW;
    float a = s + bias[c];
    float zv = zr[(b * (2 * C) + c) * HW + pix];
    float hp = hprev[i];
    out[i] = (1.0f - zv) * hp + zv * tanhf(a);
}

// ---------------------------------------------------------------------------

extern "C" void kernel_launch(void* const* d_in, const int* in_sizes, int n_in,
                              void* d_out, int out_size)
{
    const float* input   = (const float*)d_in[0];
    const float* c1_w    = (const float*)d_in[1];
    const float* c1_b    = (const float*)d_in[2];
    const float* g1_zr_w = (const float*)d_in[3];
    const float* g1_zr_b = (const float*)d_in[4];
    const float* g1_h_w  = (const float*)d_in[5];
    const float* g1_h_b  = (const float*)d_in[6];
    const float* c2_w    = (const float*)d_in[7];
    const float* c2_b    = (const float*)d_in[8];
    const float* g2_zr_w = (const float*)d_in[9];
    const float* g2_zr_b = (const float*)d_in[10];
    const float* g2_h_w  = (const float*)d_in[11];
    const float* g2_h_b  = (const float*)d_in[12];
    const float* c3_w    = (const float*)d_in[13];
    const float* c3_b    = (const float*)d_in[14];
    const float* g3_zr_w = (const float*)d_in[15];
    const float* g3_zr_b = (const float*)d_in[16];
    const float* g3_h_w  = (const float*)d_in[17];
    const float* g3_h_b  = (const float*)d_in[18];

    float *seq1, *seq2, *xts1, *xts2, *xts3, *zr, *rh, *part, *h3a, *h3b, *zero0;
    cudaGetSymbolAddress((void**)&seq1,  g_seq1);
    cudaGetSymbolAddress((void**)&seq2,  g_seq2);
    cudaGetSymbolAddress((void**)&xts1,  g_xts1);
    cudaGetSymbolAddress((void**)&xts2,  g_xts2);
    cudaGetSymbolAddress((void**)&xts3,  g_xts3);
    cudaGetSymbolAddress((void**)&zr,    g_zr);
    cudaGetSymbolAddress((void**)&rh,    g_rh);
    cudaGetSymbolAddress((void**)&part,  g_part);
    cudaGetSymbolAddress((void**)&h3a,   g_h3a);
    cudaGetSymbolAddress((void**)&h3b,   g_h3b);
    cudaGetSymbolAddress((void**)&zero0, g_zero);

    {   // zero h0 buffer
        int nz = BATCH * 64 * 64 * 64;
        zerok<<<(nz + 255) / 256, 256>>>(zero0, nz);
    }

    const size_t S1 = (size_t)BATCH * 64 * 64 * 64;   // stage1 per-t slice (2.1M)
    const size_t S2 = (size_t)BATCH * 128 * 32 * 32;  // stage2 per-t slice (1.05M)
    const size_t S3x = (size_t)BATCH * 128 * 16 * 16; // stage3 xt per-t (262k)

    // ================= Stage 1: 1 -> 64ch, 128x128 -> 64x64 =================
    // batched strided conv over all T
    conv4s2<16, 8, 8><<<dim3(4, 8, TSTEPS * BATCH * 8), dim3(16, 8)>>>(
        input, (long long)TSTEPS * 128 * 128, (long long)128 * 128,
        c1_w, c1_b, xts1, 1, 64, 128, 128);

    {
        const float* hprev = zero0;
        for (int t = 0; t < TSTEPS; t++) {
            const float* xt = xts1 + (size_t)t * S1;
            // zr fused: sigmoid + rh
            conv5<32, 16, 8, 0><<<dim3(2, 4, BATCH * 16 * 1), dim3(32, 4)>>>(
                xt, 64, hprev, 64, g1_zr_w, g1_zr_b, zr, rh, 128, 64, 64, 16, 1, 128);
            // h-conv raw split-K=2 over [xt | rh]
            conv5<32, 16, 8, 2><<<dim3(2, 4, BATCH * 8 * 2), dim3(32, 4)>>>(
                xt, 64, rh, 64, g1_h_w, nullptr, part, nullptr, 64, 64, 64, 8, 2, 64);
            float* hout = seq1 + (size_t)t * S1;
            long long n = (long long)BATCH * 64 * 4096;
            hEpiK<<<(unsigned)((n + 255) / 256), 256>>>(part, 2, g1_h_b, zr, hprev, hout, 64, 4096);
            hprev = hout;
        }
    }

    // ================= Stage 2: 64 -> 128ch, 64x64 -> 32x32 =================
    conv4s2<16, 8, 8><<<dim3(2, 4, TSTEPS * BATCH * 16), dim3(16, 8)>>>(
        seq1, (long long)64 * 4096, (long long)BATCH * 64 * 4096,
        c2_w, c2_b, xts2, 64, 128, 64, 64);

    {
        const float* hprev = zero0;
        for (int t = 0; t < TSTEPS; t++) {
            const float* xt = xts2 + (size_t)t * S2;
            // zr raw split-K=2
            conv5<32, 16, 8, 2><<<dim3(1, 2, BATCH * 32 * 2), dim3(32, 4)>>>(
                xt, 128, hprev, 128, g2_zr_w, nullptr, part, nullptr, 256, 32, 32, 32, 2, 128);
            {
                long long n = (long long)BATCH * 256 * 1024;
                zrEpiK<<<(unsigned)((n + 255) / 256), 256>>>(part, 2, g2_zr_b, hprev, zr, rh, 256, 1024);
            }
            // h raw split-K=4
            conv5<32, 16, 8, 2><<<dim3(1, 2, BATCH * 16 * 4), dim3(32, 4)>>>(
                xt, 128, rh, 128, g2_h_w, nullptr, part, nullptr, 128, 32, 32, 16, 4, 64);
            float* hout = seq2 + (size_t)t * S2;
            long long n = (long long)BATCH * 128 * 1024;
            hEpiK<<<(unsigned)((n + 255) / 256), 256>>>(part, 4, g2_h_b, zr, hprev, hout, 128, 1024);
            hprev = hout;
        }
    }

    // ================= Stage 3: 128 -> 128ch, 32x32 -> 16x16 ================
    conv4s2<16, 8, 8><<<dim3(1, 2, TSTEPS * BATCH * 16), dim3(16, 8)>>>(
        seq2, (long long)128 * 1024, (long long)BATCH * 128 * 1024,
        c3_w, c3_b, xts3, 128, 128, 32, 32);

    float* h3final = nullptr;
    {
        const float* hprev = zero0;
        float* bufs[2] = { h3a, h3b };
        for (int t = 0; t < TSTEPS; t++) {
            const float* xt = xts3 + (size_t)t * S3x;
            // zr raw split-K=8
            conv5<16, 16, 8, 2><<<dim3(1, 1, BATCH * 32 * 8), dim3(16, 4)>>>(
                xt, 128, hprev, 128, g3_zr_w, nullptr, part, nullptr, 256, 16, 16, 32, 8, 32);
            {
                long long n = (long long)BATCH * 256 * 256;
                zrEpiK<<<(unsigned)((n + 255) / 256), 256>>>(part, 8, g3_zr_b, hprev, zr, rh, 256, 256);
            }
            // h raw split-K=16
            conv5<16, 16, 8, 2><<<dim3(1, 1, BATCH * 16 * 16), dim3(16, 4)>>>(
                xt, 128, rh, 128, g3_h_w, nullptr, part, nullptr, 128, 16, 16, 16, 16, 16);
            float* hout = bufs[t & 1];
            long long n = (long long)BATCH * 128 * 256;
            hEpiK<<<(unsigned)((n + 255) / 256), 256>>>(part, 16, g3_h_b, zr, hprev, hout, 128, 256);
            hprev = hout;
            h3final = hout;
        }
    }

    // ================= Gather outputs =================
    float* out = (float*)d_out;
    int n1 = (int)S1, n2 = (int)S2, n3 = BATCH * 128 * 16 * 16;
    copyk<<<(n1 + 255) / 256, 256>>>(out, seq1 + (size_t)(TSTEPS - 1) * S1, n1);
    copyk<<<(n2 + 255) / 256, 256>>>(out + n1, seq2 + (size_t)(TSTEPS - 1) * S2, n2);
    copyk<<<(n3 + 255) / 256, 256>>>(out + n1 + n2, h3final, n3);
}

// round 4
// speedup vs baseline: 2.4379x; 1.3591x over previous
#include <cuda_runtime.h>
#include <math.h>
#include <stdint.h>

#define TSTEPS 12
#define BATCH  8

// ---------------- scratch (static device globals) ---------------------------
__device__ float g_seq1[(size_t)TSTEPS * BATCH * 64 * 64 * 64];
__device__ float g_seq2[(size_t)TSTEPS * BATCH * 128 * 32 * 32];
__device__ float g_xts1[(size_t)TSTEPS * BATCH * 64 * 64 * 64];
__device__ float g_xts2[(size_t)TSTEPS * BATCH * 128 * 32 * 32];
__device__ float g_xts3[(size_t)TSTEPS * BATCH * 128 * 16 * 16];
__device__ float g_zr  [(size_t)BATCH * 128 * 64 * 64];
__device__ float g_rh  [(size_t)BATCH * 64 * 64 * 64];
__device__ float g_part[(size_t)4194304];
__device__ float g_h3a [(size_t)BATCH * 128 * 16 * 16];
__device__ float g_h3b [(size_t)BATCH * 128 * 16 * 16];
__device__ float g_zero[(size_t)BATCH * 64 * 64 * 64];

__global__ void zerok(float* p, int n) {
    int i = blockIdx.x * blockDim.x + threadIdx.x;
    if (i < n) p[i] = 0.0f;
}
__global__ void copyk(float* __restrict__ dst, const float* __restrict__ src, int n) {
    int i = blockIdx.x * blockDim.x + threadIdx.x;
    if (i < n) dst[i] = src[i];
}

// ---------------- cp.async helpers ------------------------------------------
__device__ __forceinline__ void cp4(uint32_t saddr, const float* g, bool ok) {
    int sz = ok ? 4 : 0;
    asm volatile("cp.async.ca.shared.global [%0], [%1], 4, %2;\n"
                 :: "r"(saddr), "l"(g), "r"(sz));
}
__device__ __forceinline__ void cpCommit() {
    asm volatile("cp.async.commit_group;\n" ::: "memory");
}
template <int N>
__device__ __forceinline__ void cpWait() {
    asm volatile("cp.async.wait_group %0;\n" :: "n"(N) : "memory");
}

__device__ __forceinline__ uint32_t f2tf32(float f) {
    uint32_t u;
    asm("cvt.rna.tf32.f32 %0, %1;" : "=r"(u) : "f"(f));
    return u;
}
__device__ __forceinline__ void splitTf32(float v, uint32_t& hi, uint32_t& lo) {
    hi = f2tf32(v);
    lo = f2tf32(v - __uint_as_float(hi));
}
__device__ __forceinline__ void mma8(float* d, uint32_t a0, uint32_t a1, uint32_t a2,
                                     uint32_t a3, uint32_t b0, uint32_t b1) {
    asm volatile(
        "mma.sync.aligned.m16n8k8.row.col.f32.tf32.tf32.f32 "
        "{%0,%1,%2,%3}, {%4,%5,%6,%7}, {%8,%9}, {%0,%1,%2,%3};"
        : "+f"(d[0]), "+f"(d[1]), "+f"(d[2]), "+f"(d[3])
        : "r"(a0), "r"(a1), "r"(a2), "r"(a3), "r"(b0), "r"(b1));
}

// ---------------------------------------------------------------------------
// Strided conv k4 s2 p1, batched over T (~5% of runtime, unchanged)
// ---------------------------------------------------------------------------
template <int TX, int TY, int OC>
__global__ void conv4s2(const float* __restrict__ in,
                        long long strideB, long long strideT,
                        const float* __restrict__ w, const float* __restrict__ bias,
                        float* __restrict__ out,
                        int Cin, int Cout, int Hin, int Win)
{
    const int Hout = Hin >> 1, Wout = Win >> 1;
    const int ocG = Cout / OC;
    int z = blockIdx.z;
    const int ocb = z % ocG; z /= ocG;
    const int b   = z % BATCH;
    const int t   = z / BATCH;
    const int y0  = blockIdx.y * TY;
    const int x0  = blockIdx.x * TX;

    constexpr int IW = 2 * TX + 2;
    constexpr int IH = 2 * TY + 2;
    __shared__ float s_in[IH * IW];
    __shared__ float s_w[OC * 16];

    const int tid = threadIdx.y * TX + threadIdx.x;
    const int nth = TX * TY;
    const float* base = in + (long long)b * strideB + (long long)t * strideT;

    float acc[OC];
#pragma unroll
    for (int oc = 0; oc < OC; oc++) acc[oc] = 0.0f;

    for (int ic = 0; ic < Cin; ic++) {
        const float* src = base + (long long)ic * Hin * Win;
        for (int idx = tid; idx < IH * IW; idx += nth) {
            int iy = 2 * y0 - 1 + idx / IW;
            int ix = 2 * x0 - 1 + idx % IW;
            s_in[idx] = (iy >= 0 && iy < Hin && ix >= 0 && ix < Win)
                            ? src[(long long)iy * Win + ix] : 0.0f;
        }
        for (int idx = tid; idx < OC * 16; idx += nth) {
            int oc = idx / 16, k = idx % 16;
            s_w[idx] = w[(((long long)(ocb * OC + oc)) * Cin + ic) * 16 + k];
        }
        __syncthreads();
#pragma unroll
        for (int kh = 0; kh < 4; kh++)
#pragma unroll
            for (int kw = 0; kw < 4; kw++) {
                float inv = s_in[(2 * threadIdx.y + kh) * IW + 2 * threadIdx.x + kw];
#pragma unroll
                for (int oc = 0; oc < OC; oc++)
                    acc[oc] = fmaf(inv, s_w[oc * 16 + kh * 4 + kw], acc[oc]);
            }
        __syncthreads();
    }

    const int y = y0 + threadIdx.y, x = x0 + threadIdx.x;
#pragma unroll
    for (int oc = 0; oc < OC; oc++) {
        int c = ocb * OC + oc;
        out[(((long long)(t * BATCH + b) * Cout + c) * Hout + y) * Wout + x] = acc[oc] + bias[c];
    }
}

// ---------------------------------------------------------------------------
// 5x5 conv s1 p2, implicit GEMM with 3xTF32 error-compensated mma.sync.
// Block: 128 threads (4 warps). Tile: TX x 8 pixel rows, 16 output channels.
// Warp w handles rows [2w, 2w+2). NG = 2*(TX/8) n-groups of 8 px per warp.
// Input tiles pre-split into (hi, lo) tf32 pairs in smem once per 8-ch chunk.
// EPI 0: fused sigmoid -> zr, plus rh = r*hprev for r-half (KS must be 1).
// EPI 2: raw partial to out[ks][b][c][hw].
// blockIdx.z = ((b*ocG + ocb)*KS + ks)
// ---------------------------------------------------------------------------
template <int TX, int EPI>
__global__ void __launch_bounds__(128)
conv5mma(const float* __restrict__ src0, int C0,
         const float* __restrict__ src1, int C1,
         const float* __restrict__ w, const float* __restrict__ bias,
         float* __restrict__ out, float* __restrict__ rhOut,
         int Cout, int H, int W, int ocG, int KS, int chunkIC)
{
    constexpr int TY = 8, IW = TX + 4, IH = TY + 4, IN = IH * IW;
    constexpr int SPAD = IN + ((8 - (IN % 32) + 32) % 32);  // stride % 32 == 8
    constexpr int PB = TX / 8;
    constexpr int NG = 2 * PB;
    constexpr int SWOC = 24;
    constexpr int WN = 25 * 8 * SWOC;

    extern __shared__ float sm[];
    float* s_hi = sm;                    // [2][8][SPAD] (cp.async lands here raw)
    float* s_lo = sm + 2 * 8 * SPAD;     // [2][8][SPAD]
    float* s_w  = sm + 4 * 8 * SPAD;     // [2][WN]

    int z = blockIdx.z;
    const int ks  = z % KS;  z /= KS;
    const int ocb = z % ocG;
    const int b   = z / ocG;
    const int y0  = blockIdx.y * TY;
    const int x0  = blockIdx.x * TX;
    const int tid  = threadIdx.x;
    const int warp = tid >> 5, lane = tid & 31;
    const int gid  = lane >> 2, tig = lane & 3;

    const int Cin = C0 + C1;
    const long long HW = (long long)H * W;
    const int icBeg = ks * chunkIC;
    const int NC = chunkIC / 8;

    const uint32_t sib = (uint32_t)__cvta_generic_to_shared(s_hi);
    const uint32_t swb = (uint32_t)__cvta_generic_to_shared(s_w);

    auto fillChunk = [&](int buf, int ck) {
        const int cs = icBeg + ck * 8;   // chunks never straddle the C0 boundary
        const float* sbase = (cs < C0) ? src0 + ((long long)b * C0 + cs) * HW
                                       : src1 + ((long long)b * C1 + (cs - C0)) * HW;
        for (int idx = tid; idx < IN; idx += 128) {
            int rr = idx / IW, cc = idx - rr * IW;
            int iy = y0 - 2 + rr, ix = x0 - 2 + cc;
            bool ok = (iy >= 0) && (iy < H) && (ix >= 0) && (ix < W);
            const float* g = ok ? (sbase + (long long)iy * W + ix) : sbase;
            uint32_t d = sib + (uint32_t)(buf * 8 * SPAD + idx) * 4u;
#pragma unroll
            for (int c = 0; c < 8; c++)
                cp4(d + (uint32_t)(c * SPAD) * 4u, g + (long long)c * HW, ok);
        }
        for (int idx = tid; idx < 25 * 8 * 16; idx += 128) {
            int oc = idx & 15;
            int rest = idx >> 4;        // khkw*8 + ic
            int ic = rest & 7, khkw = rest >> 3;
            const float* g = w + ((long long)(ocb * 16 + oc) * Cin + (cs + ic)) * 25 + khkw;
            cp4(swb + (uint32_t)(buf * WN + (khkw * 8 + ic) * SWOC + oc) * 4u, g, true);
        }
    };

    float acc[NG][4];
#pragma unroll
    for (int g = 0; g < NG; g++)
#pragma unroll
        for (int j = 0; j < 4; j++) acc[g][j] = 0.0f;

    fillChunk(0, 0);
    cpCommit();

    for (int ck = 0; ck < NC; ck++) {
        const int cur = ck & 1;
        if (ck + 1 < NC) fillChunk(cur ^ 1, ck + 1);
        cpCommit();
        cpWait<1>();
        __syncthreads();

        // --- pre-split input tile: hi in place, lo in second tile ---
        {
            float* hT = s_hi + cur * 8 * SPAD;
            float* lT = s_lo + cur * 8 * SPAD;
#pragma unroll
            for (int c = 0; c < 8; c++) {
                for (int idx = tid; idx < IN; idx += 128) {
                    float v = hT[c * SPAD + idx];
                    uint32_t h, l;
                    splitTf32(v, h, l);
                    hT[c * SPAD + idx] = __uint_as_float(h);
                    lT[c * SPAD + idx] = __uint_as_float(l);
                }
            }
        }
        __syncthreads();

        const float* siH = s_hi + cur * 8 * SPAD + tig * SPAD;
        const float* siL = s_lo + cur * 8 * SPAD + tig * SPAD;
        const float* sw  = s_w + cur * WN;
        const int prow = 2 * warp;

#pragma unroll
        for (int kh = 0; kh < 5; kh++) {
#pragma unroll
            for (int kw = 0; kw < 5; kw++) {
                const float* swk = sw + (kh * 5 + kw) * 8 * SWOC;
                uint32_t aH[4], aL[4];
                splitTf32(swk[tig * SWOC + gid],           aH[0], aL[0]);
                splitTf32(swk[tig * SWOC + gid + 8],       aH[1], aL[1]);
                splitTf32(swk[(tig + 4) * SWOC + gid],     aH[2], aL[2]);
                splitTf32(swk[(tig + 4) * SWOC + gid + 8], aH[3], aL[3]);
#pragma unroll
                for (int g = 0; g < NG; g++) {
                    const int r = g / PB, pb = g % PB;
                    const int off = (prow + r + kh) * IW + 8 * pb + gid + kw;
                    uint32_t b0h = __float_as_uint(siH[off]);
                    uint32_t b1h = __float_as_uint(siH[off + 4 * SPAD]);
                    uint32_t b0l = __float_as_uint(siL[off]);
                    uint32_t b1l = __float_as_uint(siL[off + 4 * SPAD]);
                    mma8(acc[g], aH[0], aH[1], aH[2], aH[3], b0l, b1l);
                    mma8(acc[g], aL[0], aL[1], aL[2], aL[3], b0h, b1h);
                    mma8(acc[g], aH[0], aH[1], aH[2], aH[3], b0h, b1h);
                }
            }
        }
        __syncthreads();
    }

    // epilogue: d0:(gid, 2*tig) d1:(gid, 2*tig+1) d2:(gid+8, 2*tig) d3:(gid+8, 2*tig+1)
#pragma unroll
    for (int g = 0; g < NG; g++) {
        const int r = g / PB, pb = g % PB;
        const int y = y0 + 2 * warp + r;
        const int xb = x0 + 8 * pb + 2 * tig;
#pragma unroll
        for (int j = 0; j < 4; j++) {
            const int m = gid + ((j >> 1) << 3);
            const int x = xb + (j & 1);
            const int c = ocb * 16 + m;
            const long long pix = (long long)y * W + x;
            float v = acc[g][j];
            if (EPI == 0) {
                float a = v + bias[c];
                float s = 1.0f / (1.0f + expf(-a));
                out[((long long)b * Cout + c) * HW + pix] = s;
                const int Ch = Cout >> 1;
                if (c >= Ch) {
                    long long hidx = ((long long)b * Ch + (c - Ch)) * HW + pix;
                    rhOut[hidx] = s * src1[hidx];   // src1 == hprev
                }
            } else {
                out[((long long)(ks * BATCH + b) * Cout + c) * HW + pix] = v;
            }
        }
    }
}

// ---------------------------------------------------------------------------
// Split-K epilogues
// ---------------------------------------------------------------------------
__global__ void zrEpiK(const float* __restrict__ part, int KS,
                       const float* __restrict__ bias, const float* __restrict__ hprev,
                       float* __restrict__ zrOut, float* __restrict__ rhOut,
                       int C2, long long HW)
{
    const long long n = (long long)BATCH * C2 * HW;
    long long i = (long long)blockIdx.x * blockDim.x + threadIdx.x;
    if (i >= n) return;
    float s = 0.0f;
    for (int k = 0; k < KS; k++) s += part[(long long)k * n + i];
    const int c = (int)((i / HW) % C2);
    s += bias[c];
    float sg = 1.0f / (1.0f + expf(-s));
    zrOut[i] = sg;
    const int C = C2 >> 1;
    if (c >= C) {
        long long b = i / (HW * C2);
        long long pix = i % HW;
        long long hidx = (b * C + (c - C)) * HW + pix;
        rhOut[hidx] = sg * hprev[hidx];
    }
}

__global__ void hEpiK(const float* __restrict__ part, int KS,
                      const float* __restrict__ bias, const float* __restrict__ zr,
                      const float* __restrict__ hprev, float* __restrict__ out,
                      int C, long long HW)
{
    const long long n = (long long)BATCH * C * HW;
    long long i = (long long)blockIdx.x * blockDim.x + threadIdx.x;
    if (i >= n) return;
    float s = 0.0f;
    for (int k = 0; k < KS; k++) s += part[(long long)k * n + i];
    const int c = (int)((i / HW) % C);
    long long b = i / (HW * C);
    long long pix = i % HW;
    float a = s + bias[c];
    float zv = zr[(b * (2 * C) + c) * HW + pix];
    float hp = hprev[i];
    out[i] = (1.0f - zv) * hp + zv * tanhf(a);
}

// ---------------------------------------------------------------------------

extern "C" void kernel_launch(void* const* d_in, const int* in_sizes, int n_in,
                              void* d_out, int out_size)
{
    const float* input   = (const float*)d_in[0];
    const float* c1_w    = (const float*)d_in[1];
    const float* c1_b    = (const float*)d_in[2];
    const float* g1_zr_w = (const float*)d_in[3];
    const float* g1_zr_b = (const float*)d_in[4];
    const float* g1_h_w  = (const float*)d_in[5];
    const float* g1_h_b  = (const float*)d_in[6];
    const float* c2_w    = (const float*)d_in[7];
    const float* c2_b    = (const float*)d_in[8];
    const float* g2_zr_w = (const float*)d_in[9];
    const float* g2_zr_b = (const float*)d_in[10];
    const float* g2_h_w  = (const float*)d_in[11];
    const float* g2_h_b  = (const float*)d_in[12];
    const float* c3_w    = (const float*)d_in[13];
    const float* c3_b    = (const float*)d_in[14];
    const float* g3_zr_w = (const float*)d_in[15];
    const float* g3_zr_b = (const float*)d_in[16];
    const float* g3_h_w  = (const float*)d_in[17];
    const float* g3_h_b  = (const float*)d_in[18];

    float *seq1, *seq2, *xts1, *xts2, *xts3, *zr, *rh, *part, *h3a, *h3b, *zero0;
    cudaGetSymbolAddress((void**)&seq1,  g_seq1);
    cudaGetSymbolAddress((void**)&seq2,  g_seq2);
    cudaGetSymbolAddress((void**)&xts1,  g_xts1);
    cudaGetSymbolAddress((void**)&xts2,  g_xts2);
    cudaGetSymbolAddress((void**)&xts3,  g_xts3);
    cudaGetSymbolAddress((void**)&zr,    g_zr);
    cudaGetSymbolAddress((void**)&rh,    g_rh);
    cudaGetSymbolAddress((void**)&part,  g_part);
    cudaGetSymbolAddress((void**)&h3a,   g_h3a);
    cudaGetSymbolAddress((void**)&h3b,   g_h3b);
    cudaGetSymbolAddress((void**)&zero0, g_zero);

    // smem sizes: TY=8
    constexpr int IN32 = 12 * 36, SP32 = IN32 + ((8 - (IN32 % 32) + 32) % 32); // 456
    constexpr int IN16 = 12 * 20, SP16 = IN16 + ((8 - (IN16 % 32) + 32) % 32); // 264
    constexpr int WNW  = 2 * 25 * 8 * 24;
    constexpr int SM32 = (4 * 8 * SP32 + WNW) * 4;   // ~96.8 KB
    constexpr int SM16 = (4 * 8 * SP16 + WNW) * 4;   // ~72.2 KB
    cudaFuncSetAttribute(conv5mma<32, 0>, cudaFuncAttributeMaxDynamicSharedMemorySize, SM32);
    cudaFuncSetAttribute(conv5mma<32, 2>, cudaFuncAttributeMaxDynamicSharedMemorySize, SM32);
    cudaFuncSetAttribute(conv5mma<16, 2>, cudaFuncAttributeMaxDynamicSharedMemorySize, SM16);

    {   // zero h0 buffer
        int nz = BATCH * 64 * 64 * 64;
        zerok<<<(nz + 255) / 256, 256>>>(zero0, nz);
    }

    const size_t S1 = (size_t)BATCH * 64 * 64 * 64;
    const size_t S2 = (size_t)BATCH * 128 * 32 * 32;
    const size_t S3x = (size_t)BATCH * 128 * 16 * 16;

    // ================= Stage 1: 1 -> 64ch, 128x128 -> 64x64 =================
    conv4s2<16, 8, 8><<<dim3(4, 8, TSTEPS * BATCH * 8), dim3(16, 8)>>>(
        input, (long long)TSTEPS * 128 * 128, (long long)128 * 128,
        c1_w, c1_b, xts1, 1, 64, 128, 128);

    {
        const float* hprev = zero0;
        for (int t = 0; t < TSTEPS; t++) {
            const float* xt = xts1 + (size_t)t * S1;
            // zr fused (KS=1): Cout=128, ocG=8
            conv5mma<32, 0><<<dim3(2, 8, BATCH * 8), 128, SM32>>>(
                xt, 64, hprev, 64, g1_zr_w, g1_zr_b, zr, rh, 128, 64, 64, 8, 1, 128);
            // h raw split-K=2: Cout=64, ocG=4
            conv5mma<32, 2><<<dim3(2, 8, BATCH * 4 * 2), 128, SM32>>>(
                xt, 64, rh, 64, g1_h_w, nullptr, part, nullptr, 64, 64, 64, 4, 2, 64);
            float* hout = seq1 + (size_t)t * S1;
            long long n = (long long)BATCH * 64 * 4096;
            hEpiK<<<(unsigned)((n + 255) / 256), 256>>>(part, 2, g1_h_b, zr, hprev, hout, 64, 4096);
            hprev = hout;
        }
    }

    // ================= Stage 2: 64 -> 128ch, 64x64 -> 32x32 =================
    conv4s2<16, 8, 8><<<dim3(2, 4, TSTEPS * BATCH * 16), dim3(16, 8)>>>(
        seq1, (long long)64 * 4096, (long long)BATCH * 64 * 4096,
        c2_w, c2_b, xts2, 64, 128, 64, 64);

    {
        const float* hprev = zero0;
        for (int t = 0; t < TSTEPS; t++) {
            const float* xt = xts2 + (size_t)t * S2;
            // zr raw split-K=2: Cout=256, ocG=16
            conv5mma<32, 2><<<dim3(1, 4, BATCH * 16 * 2), 128, SM32>>>(
                xt, 128, hprev, 128, g2_zr_w, nullptr, part, nullptr, 256, 32, 32, 16, 2, 128);
            {
                long long n = (long long)BATCH * 256 * 1024;
                zrEpiK<<<(unsigned)((n + 255) / 256), 256>>>(part, 2, g2_zr_b, hprev, zr, rh, 256, 1024);
            }
            // h raw split-K=4: Cout=128, ocG=8
            conv5mma<32, 2><<<dim3(1, 4, BATCH * 8 * 4), 128, SM32>>>(
                xt, 128, rh, 128, g2_h_w, nullptr, part, nullptr, 128, 32, 32, 8, 4, 64);
            float* hout = seq2 + (size_t)t * S2;
            long long n = (long long)BATCH * 128 * 1024;
            hEpiK<<<(unsigned)((n + 255) / 256), 256>>>(part, 4, g2_h_b, zr, hprev, hout, 128, 1024);
            hprev = hout;
        }
    }

    // ================= Stage 3: 128 -> 128ch, 32x32 -> 16x16 ================
    conv4s2<16, 8, 8><<<dim3(1, 2, TSTEPS * BATCH * 16), dim3(16, 8)>>>(
        seq2, (long long)128 * 1024, (long long)BATCH * 128 * 1024,
        c3_w, c3_b, xts3, 128, 128, 32, 32);

    float* h3final = nullptr;
    {
        const float* hprev = zero0;
        float* bufs[2] = { h3a, h3b };
        for (int t = 0; t < TSTEPS; t++) {
            const float* xt = xts3 + (size_t)t * S3x;
            // zr raw split-K=4: Cout=256, ocG=16
            conv5mma<16, 2><<<dim3(1, 2, BATCH * 16 * 4), 128, SM16>>>(
                xt, 128, hprev, 128, g3_zr_w, nullptr, part, nullptr, 256, 16, 16, 16, 4, 64);
            {
                long long n = (long long)BATCH * 256 * 256;
                zrEpiK<<<(unsigned)((n + 255) / 256), 256>>>(part, 4, g3_zr_b, hprev, zr, rh, 256, 256);
            }
            // h raw split-K=8: Cout=128, ocG=8
            conv5mma<16, 2><<<dim3(1, 2, BATCH * 8 * 8), 128, SM16>>>(
                xt, 128, rh, 128, g3_h_w, nullptr, part, nullptr, 128, 16, 16, 8, 8, 32);
            float* hout = bufs[t & 1];
            long long n = (long long)BATCH * 128 * 256;
            hEpiK<<<(unsigned)((n + 255) / 256), 256>>>(part, 8, g3_h_b, zr, hprev, hout, 128, 256);
            hprev = hout;
            h3final = hout;
        }
    }

    // ================= Gather outputs =================
    float* out = (float*)d_out;
    int n1 = (int)S1, n2 = (int)S2, n3 = BATCH * 128 * 16 * 16;
    copyk<<<(n1 + 255) / 256, 256>>>(out, seq1 + (size_t)(TSTEPS - 1) * S1, n1);
    copyk<<<(n2 + 255) / 256, 256>>>(out + n1, seq2 + (size_t)(TSTEPS - 1) * S2, n2);
    copyk<<<(n3 + 255) / 256, 256>>>(out + n1 + n2, h3final, n3);
}

// round 5
// speedup vs baseline: 2.5056x; 1.0278x over previous
#include <cuda_runtime.h>
#include <math.h>
#include <stdint.h>

#define TSTEPS 12
#define BATCH  8

// ---------------- scratch (static device globals) ---------------------------
__device__ float g_seq1[(size_t)TSTEPS * BATCH * 64 * 64 * 64];
__device__ float g_seq2[(size_t)TSTEPS * BATCH * 128 * 32 * 32];
__device__ float g_xts1[(size_t)TSTEPS * BATCH * 64 * 64 * 64];
__device__ float g_xts2[(size_t)TSTEPS * BATCH * 128 * 32 * 32];
__device__ float g_xts3[(size_t)TSTEPS * BATCH * 128 * 16 * 16];
__device__ float g_zr  [(size_t)BATCH * 128 * 64 * 64];
__device__ float g_rh  [(size_t)BATCH * 64 * 64 * 64];
__device__ float g_part[(size_t)4194304];
__device__ float g_h3a [(size_t)BATCH * 128 * 16 * 16];
__device__ float g_h3b [(size_t)BATCH * 128 * 16 * 16];
__device__ float g_zero[(size_t)BATCH * 64 * 64 * 64];

__global__ void zerok(float* p, int n) {
    int i = blockIdx.x * blockDim.x + threadIdx.x;
    if (i < n) p[i] = 0.0f;
}
__global__ void copyk(float* __restrict__ dst, const float* __restrict__ src, int n) {
    int i = blockIdx.x * blockDim.x + threadIdx.x;
    if (i < n) dst[i] = src[i];
}

// ---------------- cp.async helpers ------------------------------------------
__device__ __forceinline__ void cp4(uint32_t saddr, const float* g, bool ok) {
    int sz = ok ? 4 : 0;
    asm volatile("cp.async.ca.shared.global [%0], [%1], 4, %2;\n"
                 :: "r"(saddr), "l"(g), "r"(sz));
}
__device__ __forceinline__ void cpCommit() {
    asm volatile("cp.async.commit_group;\n" ::: "memory");
}
template <int N>
__device__ __forceinline__ void cpWait() {
    asm volatile("cp.async.wait_group %0;\n" :: "n"(N) : "memory");
}

__device__ __forceinline__ uint32_t f2tf32(float f) {
    uint32_t u;
    asm("cvt.rna.tf32.f32 %0, %1;" : "=r"(u) : "f"(f));
    return u;
}
__device__ __forceinline__ void splitTf32(float v, uint32_t& hi, uint32_t& lo) {
    hi = f2tf32(v);
    lo = f2tf32(v - __uint_as_float(hi));
}
__device__ __forceinline__ void mma8(float* d, uint32_t a0, uint32_t a1, uint32_t a2,
                                     uint32_t a3, uint32_t b0, uint32_t b1) {
    asm volatile(
        "mma.sync.aligned.m16n8k8.row.col.f32.tf32.tf32.f32 "
        "{%0,%1,%2,%3}, {%4,%5,%6,%7}, {%8,%9}, {%0,%1,%2,%3};"
        : "+f"(d[0]), "+f"(d[1]), "+f"(d[2]), "+f"(d[3])
        : "r"(a0), "r"(a1), "r"(a2), "r"(a3), "r"(b0), "r"(b1));
}

// ---------------------------------------------------------------------------
// Strided conv k4 s2 p1, batched over T (~5% of runtime, unchanged)
// ---------------------------------------------------------------------------
template <int TX, int TY, int OC>
__global__ void conv4s2(const float* __restrict__ in,
                        long long strideB, long long strideT,
                        const float* __restrict__ w, const float* __restrict__ bias,
                        float* __restrict__ out,
                        int Cin, int Cout, int Hin, int Win)
{
    const int Hout = Hin >> 1, Wout = Win >> 1;
    const int ocG = Cout / OC;
    int z = blockIdx.z;
    const int ocb = z % ocG; z /= ocG;
    const int b   = z % BATCH;
    const int t   = z / BATCH;
    const int y0  = blockIdx.y * TY;
    const int x0  = blockIdx.x * TX;

    constexpr int IW = 2 * TX + 2;
    constexpr int IH = 2 * TY + 2;
    __shared__ float s_in[IH * IW];
    __shared__ float s_w[OC * 16];

    const int tid = threadIdx.y * TX + threadIdx.x;
    const int nth = TX * TY;
    const float* base = in + (long long)b * strideB + (long long)t * strideT;

    float acc[OC];
#pragma unroll
    for (int oc = 0; oc < OC; oc++) acc[oc] = 0.0f;

    for (int ic = 0; ic < Cin; ic++) {
        const float* src = base + (long long)ic * Hin * Win;
        for (int idx = tid; idx < IH * IW; idx += nth) {
            int iy = 2 * y0 - 1 + idx / IW;
            int ix = 2 * x0 - 1 + idx % IW;
            s_in[idx] = (iy >= 0 && iy < Hin && ix >= 0 && ix < Win)
                            ? src[(long long)iy * Win + ix] : 0.0f;
        }
        for (int idx = tid; idx < OC * 16; idx += nth) {
            int oc = idx / 16, k = idx % 16;
            s_w[idx] = w[(((long long)(ocb * OC + oc)) * Cin + ic) * 16 + k];
        }
        __syncthreads();
#pragma unroll
        for (int kh = 0; kh < 4; kh++)
#pragma unroll
            for (int kw = 0; kw < 4; kw++) {
                float inv = s_in[(2 * threadIdx.y + kh) * IW + 2 * threadIdx.x + kw];
#pragma unroll
                for (int oc = 0; oc < OC; oc++)
                    acc[oc] = fmaf(inv, s_w[oc * 16 + kh * 4 + kw], acc[oc]);
            }
        __syncthreads();
    }

    const int y = y0 + threadIdx.y, x = x0 + threadIdx.x;
#pragma unroll
    for (int oc = 0; oc < OC; oc++) {
        int c = ocb * OC + oc;
        out[(((long long)(t * BATCH + b) * Cout + c) * Hout + y) * Wout + x] = acc[oc] + bias[c];
    }
}

// ---------------------------------------------------------------------------
// 5x5 conv s1 p2, implicit GEMM with 3xTF32 error-compensated mma.sync.
// Block: 128 threads (4 warps). Tile: TX x 8 pixel rows, 16 output channels.
// smem: hi tile double-buffered, lo tile SINGLE-buffered (produced post-wait;
// end-of-loop barrier protects reuse), weights double-buffered stride 16.
// EPI 0: fused sigmoid -> zr, plus rh = r*hprev for r-half (KS must be 1).
// EPI 2: raw partial to out[ks][b][c][hw].
// blockIdx.z = ((b*ocG + ocb)*KS + ks)
// ---------------------------------------------------------------------------
template <int TX, int EPI>
__global__ void __launch_bounds__(128)
conv5mma(const float* __restrict__ src0, int C0,
         const float* __restrict__ src1, int C1,
         const float* __restrict__ w, const float* __restrict__ bias,
         float* __restrict__ out, float* __restrict__ rhOut,
         int Cout, int H, int W, int ocG, int KS, int chunkIC)
{
    constexpr int TY = 8, IW = TX + 4, IH = TY + 4, IN = IH * IW;
    constexpr int SPAD = IN + ((8 - (IN % 32) + 32) % 32);  // stride % 32 == 8
    constexpr int PB = TX / 8;
    constexpr int NG = 2 * PB;
    constexpr int SWOC = 16;                 // 2-way conflict on A-loads, tolerable
    constexpr int WN = 25 * 8 * SWOC;

    extern __shared__ float sm[];
    float* s_hi = sm;                    // [2][8][SPAD] (cp.async lands here raw)
    float* s_lo = sm + 2 * 8 * SPAD;     // [8][SPAD]  (single buffer)
    float* s_w  = sm + 3 * 8 * SPAD;     // [2][WN]

    int z = blockIdx.z;
    const int ks  = z % KS;  z /= KS;
    const int ocb = z % ocG;
    const int b   = z / ocG;
    const int y0  = blockIdx.y * TY;
    const int x0  = blockIdx.x * TX;
    const int tid  = threadIdx.x;
    const int warp = tid >> 5, lane = tid & 31;
    const int gid  = lane >> 2, tig = lane & 3;

    const int Cin = C0 + C1;
    const long long HW = (long long)H * W;
    const int icBeg = ks * chunkIC;
    const int NC = chunkIC / 8;

    const uint32_t sib = (uint32_t)__cvta_generic_to_shared(s_hi);
    const uint32_t swb = (uint32_t)__cvta_generic_to_shared(s_w);

    auto fillChunk = [&](int buf, int ck) {
        const int cs = icBeg + ck * 8;   // chunks never straddle the C0 boundary
        const float* sbase = (cs < C0) ? src0 + ((long long)b * C0 + cs) * HW
                                       : src1 + ((long long)b * C1 + (cs - C0)) * HW;
        for (int idx = tid; idx < IN; idx += 128) {
            int rr = idx / IW, cc = idx - rr * IW;
            int iy = y0 - 2 + rr, ix = x0 - 2 + cc;
            bool ok = (iy >= 0) && (iy < H) && (ix >= 0) && (ix < W);
            const float* g = ok ? (sbase + (long long)iy * W + ix) : sbase;
            uint32_t d = sib + (uint32_t)(buf * 8 * SPAD + idx) * 4u;
#pragma unroll
            for (int c = 0; c < 8; c++)
                cp4(d + (uint32_t)(c * SPAD) * 4u, g + (long long)c * HW, ok);
        }
        for (int idx = tid; idx < 25 * 8 * 16; idx += 128) {
            int oc = idx & 15;
            int rest = idx >> 4;        // khkw*8 + ic
            int ic = rest & 7, khkw = rest >> 3;
            const float* g = w + ((long long)(ocb * 16 + oc) * Cin + (cs + ic)) * 25 + khkw;
            cp4(swb + (uint32_t)(buf * WN + (khkw * 8 + ic) * SWOC + oc) * 4u, g, true);
        }
    };

    float acc[NG][4];
#pragma unroll
    for (int g = 0; g < NG; g++)
#pragma unroll
        for (int j = 0; j < 4; j++) acc[g][j] = 0.0f;

    fillChunk(0, 0);
    cpCommit();

    for (int ck = 0; ck < NC; ck++) {
        const int cur = ck & 1;
        if (ck + 1 < NC) fillChunk(cur ^ 1, ck + 1);
        cpCommit();
        cpWait<1>();
        __syncthreads();

        // --- pre-split input tile: hi in place, lo into single-buffer tile ---
        {
            float* hT = s_hi + cur * 8 * SPAD;
            float* lT = s_lo;
#pragma unroll
            for (int c = 0; c < 8; c++) {
                for (int idx = tid; idx < IN; idx += 128) {
                    float v = hT[c * SPAD + idx];
                    uint32_t h, l;
                    splitTf32(v, h, l);
                    hT[c * SPAD + idx] = __uint_as_float(h);
                    lT[c * SPAD + idx] = __uint_as_float(l);
                }
            }
        }
        __syncthreads();

        const float* siH = s_hi + cur * 8 * SPAD + tig * SPAD;
        const float* siL = s_lo + tig * SPAD;
        const float* sw  = s_w + cur * WN;
        const int prow = 2 * warp;

#pragma unroll
        for (int kh = 0; kh < 5; kh++) {
#pragma unroll
            for (int kw = 0; kw < 5; kw++) {
                const float* swk = sw + (kh * 5 + kw) * 8 * SWOC;
                uint32_t aH[4], aL[4];
                splitTf32(swk[tig * SWOC + gid],           aH[0], aL[0]);
                splitTf32(swk[tig * SWOC + gid + 8],       aH[1], aL[1]);
                splitTf32(swk[(tig + 4) * SWOC + gid],     aH[2], aL[2]);
                splitTf32(swk[(tig + 4) * SWOC + gid + 8], aH[3], aL[3]);
#pragma unroll
                for (int g = 0; g < NG; g++) {
                    const int r = g / PB, pb = g % PB;
                    const int off = (prow + r + kh) * IW + 8 * pb + gid + kw;
                    uint32_t b0h = __float_as_uint(siH[off]);
                    uint32_t b1h = __float_as_uint(siH[off + 4 * SPAD]);
                    uint32_t b0l = __float_as_uint(siL[off]);
                    uint32_t b1l = __float_as_uint(siL[off + 4 * SPAD]);
                    mma8(acc[g], aH[0], aH[1], aH[2], aH[3], b0l, b1l);
                    mma8(acc[g], aL[0], aL[1], aL[2], aL[3], b0h, b1h);
                    mma8(acc[g], aH[0], aH[1], aH[2], aH[3], b0h, b1h);
                }
            }
        }
        __syncthreads();
    }

    // epilogue: d0:(gid, 2*tig) d1:(gid, 2*tig+1) d2:(gid+8, 2*tig) d3:(gid+8, 2*tig+1)
#pragma unroll
    for (int g = 0; g < NG; g++) {
        const int r = g / PB, pb = g % PB;
        const int y = y0 + 2 * warp + r;
        const int xb = x0 + 8 * pb + 2 * tig;
#pragma unroll
        for (int j = 0; j < 4; j++) {
            const int m = gid + ((j >> 1) << 3);
            const int x = xb + (j & 1);
            const int c = ocb * 16 + m;
            const long long pix = (long long)y * W + x;
            float v = acc[g][j];
            if (EPI == 0) {
                float a = v + bias[c];
                float s = 1.0f / (1.0f + expf(-a));
                out[((long long)b * Cout + c) * HW + pix] = s;
                const int Ch = Cout >> 1;
                if (c >= Ch) {
                    long long hidx = ((long long)b * Ch + (c - Ch)) * HW + pix;
                    rhOut[hidx] = s * src1[hidx];   // src1 == hprev
                }
            } else {
                out[((long long)(ks * BATCH + b) * Cout + c) * HW + pix] = v;
            }
        }
    }
}

// ---------------------------------------------------------------------------
// Split-K epilogues
// ---------------------------------------------------------------------------
__global__ void zrEpiK(const float* __restrict__ part, int KS,
                       const float* __restrict__ bias, const float* __restrict__ hprev,
                       float* __restrict__ zrOut, float* __restrict__ rhOut,
                       int C2, long long HW)
{
    const long long n = (long long)BATCH * C2 * HW;
    long long i = (long long)blockIdx.x * blockDim.x + threadIdx.x;
    if (i >= n) return;
    float s = 0.0f;
    for (int k = 0; k < KS; k++) s += part[(long long)k * n + i];
    const int c = (int)((i / HW) % C2);
    s += bias[c];
    float sg = 1.0f / (1.0f + expf(-s));
    zrOut[i] = sg;
    const int C = C2 >> 1;
    if (c >= C) {
        long long b = i / (HW * C2);
        long long pix = i % HW;
        long long hidx = (b * C + (c - C)) * HW + pix;
        rhOut[hidx] = sg * hprev[hidx];
    }
}

__global__ void hEpiK(const float* __restrict__ part, int KS,
                      const float* __restrict__ bias, const float* __restrict__ zr,
                      const float* __restrict__ hprev, float* __restrict__ out,
                      int C, long long HW)
{
    const long long n = (long long)BATCH * C * HW;
    long long i = (long long)blockIdx.x * blockDim.x + threadIdx.x;
    if (i >= n) return;
    float s = 0.0f;
    for (int k = 0; k < KS; k++) s += part[(long long)k * n + i];
    const int c = (int)((i / HW) % C);
    long long b = i / (HW * C);
    long long pix = i % HW;
    float a = s + bias[c];
    float zv = zr[(b * (2 * C) + c) * HW + pix];
    float hp = hprev[i];
    out[i] = (1.0f - zv) * hp + zv * tanhf(a);
}

// ---------------------------------------------------------------------------

extern "C" void kernel_launch(void* const* d_in, const int* in_sizes, int n_in,
                              void* d_out, int out_size)
{
    const float* input   = (const float*)d_in[0];
    const float* c1_w    = (const float*)d_in[1];
    const float* c1_b    = (const float*)d_in[2];
    const float* g1_zr_w = (const float*)d_in[3];
    const float* g1_zr_b = (const float*)d_in[4];
    const float* g1_h_w  = (const float*)d_in[5];
    const float* g1_h_b  = (const float*)d_in[6];
    const float* c2_w    = (const float*)d_in[7];
    const float* c2_b    = (const float*)d_in[8];
    const float* g2_zr_w = (const float*)d_in[9];
    const float* g2_zr_b = (const float*)d_in[10];
    const float* g2_h_w  = (const float*)d_in[11];
    const float* g2_h_b  = (const float*)d_in[12];
    const float* c3_w    = (const float*)d_in[13];
    const float* c3_b    = (const float*)d_in[14];
    const float* g3_zr_w = (const float*)d_in[15];
    const float* g3_zr_b = (const float*)d_in[16];
    const float* g3_h_w  = (const float*)d_in[17];
    const float* g3_h_b  = (const float*)d_in[18];

    float *seq1, *seq2, *xts1, *xts2, *xts3, *zr, *rh, *part, *h3a, *h3b, *zero0;
    cudaGetSymbolAddress((void**)&seq1,  g_seq1);
    cudaGetSymbolAddress((void**)&seq2,  g_seq2);
    cudaGetSymbolAddress((void**)&xts1,  g_xts1);
    cudaGetSymbolAddress((void**)&xts2,  g_xts2);
    cudaGetSymbolAddress((void**)&xts3,  g_xts3);
    cudaGetSymbolAddress((void**)&zr,    g_zr);
    cudaGetSymbolAddress((void**)&rh,    g_rh);
    cudaGetSymbolAddress((void**)&part,  g_part);
    cudaGetSymbolAddress((void**)&h3a,   g_h3a);
    cudaGetSymbolAddress((void**)&h3b,   g_h3b);
    cudaGetSymbolAddress((void**)&zero0, g_zero);

    // smem sizes: TY=8, hi double + lo single + weights double (stride 16)
    constexpr int IN32 = 12 * 36, SP32 = IN32 + ((8 - (IN32 % 32) + 32) % 32); // 456
    constexpr int IN16 = 12 * 20, SP16 = IN16 + ((8 - (IN16 % 32) + 32) % 32); // 264
    constexpr int WNW  = 2 * 25 * 8 * 16;
    constexpr int SM32 = (3 * 8 * SP32 + WNW) * 4;   // ~67.8 KB -> 3 blocks/SM
    constexpr int SM16 = (3 * 8 * SP16 + WNW) * 4;   // ~49.8 KB -> 4 blocks/SM
    cudaFuncSetAttribute(conv5mma<32, 0>, cudaFuncAttributeMaxDynamicSharedMemorySize, SM32);
    cudaFuncSetAttribute(conv5mma<32, 2>, cudaFuncAttributeMaxDynamicSharedMemorySize, SM32);
    cudaFuncSetAttribute(conv5mma<16, 2>, cudaFuncAttributeMaxDynamicSharedMemorySize, SM16);

    {   // zero h0 buffer
        int nz = BATCH * 64 * 64 * 64;
        zerok<<<(nz + 255) / 256, 256>>>(zero0, nz);
    }

    const size_t S1 = (size_t)BATCH * 64 * 64 * 64;
    const size_t S2 = (size_t)BATCH * 128 * 32 * 32;
    const size_t S3x = (size_t)BATCH * 128 * 16 * 16;

    // ================= Stage 1: 1 -> 64ch, 128x128 -> 64x64 =================
    conv4s2<16, 8, 8><<<dim3(4, 8, TSTEPS * BATCH * 8), dim3(16, 8)>>>(
        input, (long long)TSTEPS * 128 * 128, (long long)128 * 128,
        c1_w, c1_b, xts1, 1, 64, 128, 128);

    {
        const float* hprev = zero0;
        for (int t = 0; t < TSTEPS; t++) {
            const float* xt = xts1 + (size_t)t * S1;
            // zr fused (KS=1): Cout=128, ocG=8
            conv5mma<32, 0><<<dim3(2, 8, BATCH * 8), 128, SM32>>>(
                xt, 64, hprev, 64, g1_zr_w, g1_zr_b, zr, rh, 128, 64, 64, 8, 1, 128);
            // h raw split-K=2: Cout=64, ocG=4
            conv5mma<32, 2><<<dim3(2, 8, BATCH * 4 * 2), 128, SM32>>>(
                xt, 64, rh, 64, g1_h_w, nullptr, part, nullptr, 64, 64, 64, 4, 2, 64);
            float* hout = seq1 + (size_t)t * S1;
            long long n = (long long)BATCH * 64 * 4096;
            hEpiK<<<(unsigned)((n + 255) / 256), 256>>>(part, 2, g1_h_b, zr, hprev, hout, 64, 4096);
            hprev = hout;
        }
    }

    // ================= Stage 2: 64 -> 128ch, 64x64 -> 32x32 =================
    conv4s2<16, 8, 8><<<dim3(2, 4, TSTEPS * BATCH * 16), dim3(16, 8)>>>(
        seq1, (long long)64 * 4096, (long long)BATCH * 64 * 4096,
        c2_w, c2_b, xts2, 64, 128, 64, 64);

    {
        const float* hprev = zero0;
        for (int t = 0; t < TSTEPS; t++) {
            const float* xt = xts2 + (size_t)t * S2;
            // zr raw split-K=2: Cout=256, ocG=16
            conv5mma<32, 2><<<dim3(1, 4, BATCH * 16 * 2), 128, SM32>>>(
                xt, 128, hprev, 128, g2_zr_w, nullptr, part, nullptr, 256, 32, 32, 16, 2, 128);
            {
                long long n = (long long)BATCH * 256 * 1024;
                zrEpiK<<<(unsigned)((n + 255) / 256), 256>>>(part, 2, g2_zr_b, hprev, zr, rh, 256, 1024);
            }
            // h raw split-K=4: Cout=128, ocG=8
            conv5mma<32, 2><<<dim3(1, 4, BATCH * 8 * 4), 128, SM32>>>(
                xt, 128, rh, 128, g2_h_w, nullptr, part, nullptr, 128, 32, 32, 8, 4, 64);
            float* hout = seq2 + (size_t)t * S2;
            long long n = (long long)BATCH * 128 * 1024;
            hEpiK<<<(unsigned)((n + 255) / 256), 256>>>(part, 4, g2_h_b, zr, hprev, hout, 128, 1024);
            hprev = hout;
        }
    }

    // ================= Stage 3: 128 -> 128ch, 32x32 -> 16x16 ================
    conv4s2<16, 8, 8><<<dim3(1, 2, TSTEPS * BATCH * 16), dim3(16, 8)>>>(
        seq2, (long long)128 * 1024, (long long)BATCH * 128 * 1024,
        c3_w, c3_b, xts3, 128, 128, 32, 32);

    float* h3final = nullptr;
    {
        const float* hprev = zero0;
        float* bufs[2] = { h3a, h3b };
        for (int t = 0; t < TSTEPS; t++) {
            const float* xt = xts3 + (size_t)t * S3x;
            // zr raw split-K=4: Cout=256, ocG=16
            conv5mma<16, 2><<<dim3(1, 2, BATCH * 16 * 4), 128, SM16>>>(
                xt, 128, hprev, 128, g3_zr_w, nullptr, part, nullptr, 256, 16, 16, 16, 4, 64);
            {
                long long n = (long long)BATCH * 256 * 256;
                zrEpiK<<<(unsigned)((n + 255) / 256), 256>>>(part, 4, g3_zr_b, hprev, zr, rh, 256, 256);
            }
            // h raw split-K=8: Cout=128, ocG=8
            conv5mma<16, 2><<<dim3(1, 2, BATCH * 8 * 8), 128, SM16>>>(
                xt, 128, rh, 128, g3_h_w, nullptr, part, nullptr, 128, 16, 16, 8, 8, 32);
            float* hout = bufs[t & 1];
            long long n = (long long)BATCH * 128 * 256;
            hEpiK<<<(unsigned)((n + 255) / 256), 256>>>(part, 8, g3_h_b, zr, hprev, hout, 128, 256);
            hprev = hout;
            h3final = hout;
        }
    }

    // ================= Gather outputs =================
    float* out = (float*)d_out;
    int n1 = (int)S1, n2 = (int)S2, n3 = BATCH * 128 * 16 * 16;
    copyk<<<(n1 + 255) / 256, 256>>>(out, seq1 + (size_t)(TSTEPS - 1) * S1, n1);
    copyk<<<(n2 + 255) / 256, 256>>>(out + n1, seq2 + (size_t)(TSTEPS - 1) * S2, n2);
    copyk<<<(n3 + 255) / 256, 256>>>(out + n1 + n2, h3final, n3);
}